// round 11
// baseline (speedup 1.0000x reference)
#include <cuda_runtime.h>
#include <math.h>

#define TT 512
#define BB 128
#define DD 128
#define HH 256
#define CC 10
#define G4 1024
#define MROWS (TT*BB)
#define NCTA 128
#define NGRP 8            // CTAs per barrier group = one (dir, batch-tile)

// ---------------- static device scratch (no runtime allocation) ----------------
__device__ float g_e  [(size_t)MROWS * DD];
__device__ float g_XwF[(size_t)MROWS * G4];
__device__ float g_XwB[(size_t)MROWS * G4];
__device__ float g_seq[(size_t)MROWS * 2 * HH];
__device__ float g_state[4 * BB * HH];             // per dir: h parity buf0, buf1
__device__ unsigned g_bcount[16 * 32];
__device__ unsigned g_bepoch[16 * 32];

__device__ __forceinline__ void ffma2(float2 &d, float2 a, float2 b) {
    asm("fma.rn.f32x2 %0, %1, %2, %0;"
        : "+l"(*reinterpret_cast<unsigned long long*>(&d))
        : "l"(*reinterpret_cast<unsigned long long*>(&a)),
          "l"(*reinterpret_cast<unsigned long long*>(&b)));
}

__device__ __forceinline__ float sigf(float x) {
    return __fdividef(1.0f, 1.0f + __expf(-x));
}
__device__ __forceinline__ float tanhfast(float x) {
    return __fdividef(2.0f, 1.0f + __expf(-2.0f * x)) - 1.0f;
}

__device__ __forceinline__ void cpa16(unsigned dst, const void* src) {
    asm volatile("cp.async.cg.shared.global [%0], [%1], 16;" :: "r"(dst), "l"(src));
}
#define CPA_COMMIT() asm volatile("cp.async.commit_group;")
#define CPA_WAIT0()  asm volatile("cp.async.wait_group 0;")

__device__ __forceinline__ unsigned f2tf32(float x) {
    unsigned r; asm("cvt.rna.tf32.f32 %0, %1;" : "=r"(r) : "f"(x)); return r;
}
__device__ __forceinline__ void mma_tf32(float* c, const unsigned* a, const unsigned* b) {
    asm("mma.sync.aligned.m16n8k8.row.col.f32.tf32.tf32.f32 "
        "{%0,%1,%2,%3}, {%4,%5,%6,%7}, {%8,%9}, {%0,%1,%2,%3};"
        : "+f"(c[0]), "+f"(c[1]), "+f"(c[2]), "+f"(c[3])
        : "r"(a[0]), "r"(a[1]), "r"(a[2]), "r"(a[3]), "r"(b[0]), "r"(b[1]));
}

// per-group software barrier: 8 CTAs sharing one (dir, batch-tile)  [R7, measured best]
__device__ __forceinline__ void grid_bar(int grp, unsigned &epoch) {
    __threadfence();
    __syncthreads();
    if (threadIdx.x == 0) {
        unsigned* cnt = &g_bcount[grp * 32];
        unsigned* ep  = &g_bepoch[grp * 32];
        if (atomicAdd(cnt, 1) == NGRP - 1) {
            atomicExch(cnt, 0);
            __threadfence();
            atomicAdd(ep, 1);
        } else {
            while (*(volatile unsigned*)ep == epoch) { }
        }
        epoch++;
    }
    __syncthreads();
}

// ---------------- embedding gather ----------------
__global__ void embed_k(const int* __restrict__ x, const float* __restrict__ emb) {
    int gid = blockIdx.x * blockDim.x + threadIdx.x;
    int r  = gid >> 5;
    int c4 = gid & 31;
    int t  = r >> 7;
    int b  = r & 127;
    int tok = x[b * TT + t];
    reinterpret_cast<float4*>(g_e)[(size_t)r * 32 + c4] =
        reinterpret_cast<const float4*>(emb)[(size_t)tok * 32 + c4];
}

// ---------------- 3xTF32 tensor-core GEMM + bias (unchanged from R7) ----------------
#define AS_LD 20
#define BS_LD 136
__global__ __launch_bounds__(256) void gemm_k(int a_sel, int c_sel,
        const float* __restrict__ W, const float* __restrict__ bias, int K)
{
    const float* A = a_sel ? g_seq : g_e;
    float*       C = c_sel ? g_XwB : g_XwF;

    __shared__ __align__(16) float As[2][128][AS_LD];
    __shared__ __align__(16) float Bs[2][16][BS_LD];

    const int m0   = blockIdx.x * 128;
    const int n0   = blockIdx.y * 128;
    const int tid  = threadIdx.x;
    const int lane = tid & 31;
    const int warp = tid >> 5;
    const int gid  = lane >> 2;
    const int tig  = lane & 3;
    const int wm   = warp & 3;
    const int wn   = warp >> 2;

    const unsigned sA = (unsigned)__cvta_generic_to_shared(&As[0][0][0]);
    const unsigned sB = (unsigned)__cvta_generic_to_shared(&Bs[0][0][0]);
    const unsigned bufA = 128 * AS_LD * 4;
    const unsigned bufB = 16 * BS_LD * 4;

    float acc[2][8][4];
#pragma unroll
    for (int mb = 0; mb < 2; ++mb)
#pragma unroll
        for (int nb = 0; nb < 8; ++nb)
#pragma unroll
            for (int r = 0; r < 4; ++r) acc[mb][nb][r] = 0.f;

    const int nk = K >> 4;

    auto load_tile = [&](int buf, int kt) {
#pragma unroll
        for (int i = 0; i < 2; ++i) {
            int id = tid + i * 256;
            int r = id >> 2, kq = id & 3;
            cpa16(sA + buf * bufA + (unsigned)((r * AS_LD + kq * 4) * 4),
                  A + (size_t)(m0 + r) * K + kt + kq * 4);
        }
#pragma unroll
        for (int i = 0; i < 2; ++i) {
            int id = tid + i * 256;
            int r = id >> 5, c4 = (id & 31) * 4;
            cpa16(sB + buf * bufB + (unsigned)((r * BS_LD + c4) * 4),
                  W + (size_t)(kt + r) * G4 + n0 + c4);
        }
        CPA_COMMIT();
    };

    load_tile(0, 0);
    CPA_WAIT0();
    __syncthreads();

    for (int kt = 0; kt < nk; ++kt) {
        const int cur = kt & 1;
        const bool more = (kt + 1) < nk;
        if (more) load_tile(cur ^ 1, (kt + 1) << 4);

#pragma unroll
        for (int kh = 0; kh < 2; ++kh) {
            const int k0 = kh * 8;
            unsigned ahi[2][4], alo[2][4];
#pragma unroll
            for (int mb = 0; mb < 2; ++mb) {
                const int rbase = wm * 32 + mb * 16 + gid;
#pragma unroll
                for (int r = 0; r < 4; ++r) {
                    float v = As[cur][rbase + (r & 1) * 8][k0 + tig + (r >> 1) * 4];
                    unsigned h = f2tf32(v);
                    ahi[mb][r] = h;
                    alo[mb][r] = f2tf32(v - __uint_as_float(h));
                }
            }
#pragma unroll
            for (int nb = 0; nb < 8; ++nb) {
                const int nc = wn * 64 + nb * 8 + gid;
                float b0 = Bs[cur][k0 + tig][nc];
                float b1 = Bs[cur][k0 + tig + 4][nc];
                unsigned bh[2], bl[2];
                bh[0] = f2tf32(b0); bl[0] = f2tf32(b0 - __uint_as_float(bh[0]));
                bh[1] = f2tf32(b1); bl[1] = f2tf32(b1 - __uint_as_float(bh[1]));
#pragma unroll
                for (int mb = 0; mb < 2; ++mb) mma_tf32(acc[mb][nb], ahi[mb], bh);
#pragma unroll
                for (int mb = 0; mb < 2; ++mb) mma_tf32(acc[mb][nb], ahi[mb], bl);
#pragma unroll
                for (int mb = 0; mb < 2; ++mb) mma_tf32(acc[mb][nb], alo[mb], bh);
            }
        }
        if (more) {
            CPA_WAIT0();
            __syncthreads();
        }
    }

#pragma unroll
    for (int mb = 0; mb < 2; ++mb) {
        const int row0 = m0 + wm * 32 + mb * 16 + gid;
#pragma unroll
        for (int nb = 0; nb < 8; ++nb) {
            const int col = n0 + wn * 64 + nb * 8 + tig * 2;
            float2 bv = *reinterpret_cast<const float2*>(bias + col);
            float2 v0 = make_float2(acc[mb][nb][0] + bv.x, acc[mb][nb][1] + bv.y);
            float2 v1 = make_float2(acc[mb][nb][2] + bv.x, acc[mb][nb][3] + bv.y);
            *reinterpret_cast<float2*>(C + (size_t)row0 * G4 + col)       = v0;
            *reinterpret_cast<float2*>(C + (size_t)(row0 + 8) * G4 + col) = v1;
        }
    }
}

// ---------------- persistent bidirectional LSTM: gate-split, 256 threads ------------
// bid = dir*64 + bt*8 + nt. R7 exchange (global h double buffer, atomic 8-CTA group
// barrier). Thread org: g2 = tid>>7 selects the gate PAIR (g2=0 -> i,f; g2=1 -> g,o);
// inner = tid&127 as in R7 (2 rows x 2 cols), but k stays whole per thread.
// Per warp per k: 4 FFMA2 + 1 LDS.128 (gate-paired U float4 = this thread's operand)
// + h broadcast -> FMA-pipe-bound with 2 warps/SMSP hiding latency.
// Gate recombination via small smem exchange; g2=0 threads own c and the h update.
__global__ __launch_bounds__(256) void lstm_persist_k(
        const float* __restrict__ Uf, const float* __restrict__ Ub, int write_seq)
{
    extern __shared__ float smp[];
    float*  Us = smp;                                            // 32768 floats (128 KB)
    float (*sh)[260] = reinterpret_cast<float (*)[260]>(smp + 32768);    // h stage 16x260
    float2 (*ex)[130] = reinterpret_cast<float2 (*)[130]>(smp + 32768 + 16 * 260); // [4][130]

    const int bid = blockIdx.x;
    const int dir = bid >> 6;
    const int bt  = (bid >> 3) & 7;
    const int nt  = bid & 7;
    const int grp = bid >> 3;
    const int tid = threadIdx.x;
    const int g2    = tid >> 7;        // gate pair: 0 -> gates 0,1 (i,f); 1 -> gates 2,3 (g,o)
    const int inner = tid & 127;

    const float* U  = dir ? Ub : Uf;
    const float* Xw = dir ? g_XwB : g_XwF;
    float* hbuf = g_state + (size_t)dir * 2 * BB * HH;

    // U smem, gate-paired: float4 idx = k*32 + ng*2 + gp holds
    // (U[k][2gp*HH+col], U[k][2gp*HH+col+1], U[k][(2gp+1)*HH+col], U[k][(2gp+1)*HH+col+1])
    // with col = nt*32 + ng*2
    for (int i = tid; i < 256 * 32; i += 256) {
        int k   = i >> 5;
        int f4  = i & 31;
        int ng  = f4 >> 1;
        int gp  = f4 & 1;
        int col = nt * 32 + ng * 2;
        const float* src = U + (size_t)k * G4 + (2 * gp) * HH + col;
        float2 a = *reinterpret_cast<const float2*>(src);
        float2 b = *reinterpret_cast<const float2*>(src + HH);
        reinterpret_cast<float4*>(Us)[i] = make_float4(a.x, a.y, b.x, b.y);
    }

    // zero my (bt, nt) patch of both h parity buffers
    for (int i = tid; i < 512; i += 256) {
        int r  = bt * 16 + (i >> 5);
        int cc = nt * 32 + (i & 31);
        __stcg(hbuf + (size_t)r * HH + cc, 0.f);
        __stcg(hbuf + (size_t)BB * HH + (size_t)r * HH + cc, 0.f);
    }

    unsigned epoch = 0;
    if (tid == 0) epoch = *(volatile unsigned*)&g_bepoch[grp * 32];
    grid_bar(grp, epoch);

    const int b_half = inner >> 4;
    const int n_grp  = inner & 15;
    const int nloc   = n_grp * 2;
    const int ngl    = nt * 32 + nloc;
    const int r0     = bt * 16 + b_half * 2;

    float2 cst[2] = {make_float2(0.f, 0.f), make_float2(0.f, 0.f)};  // g2==0 only

    for (int s = 0; s < TT; ++s) {
        const int t   = dir ? (TT - 1 - s) : s;
        const int par = s & 1;
        const float* hRead  = hbuf + (size_t)par * BB * HH;
        float*       hWrite = hbuf + (size_t)(par ^ 1) * BB * HH;

        // stage h tile (16 x 256): 1024 float4, 4 per thread
#pragma unroll
        for (int i = 0; i < 4; ++i) {
            int f = tid + i * 256;
            int r = f >> 6, cq = f & 63;
            *reinterpret_cast<float4*>(&sh[r][cq * 4]) =
                __ldcg(reinterpret_cast<const float4*>(
                    hRead + (size_t)(bt * 16 + r) * HH + cq * 4));
        }
        // Xw for MY gate pair, 2 rows
        const float* xwb = Xw + ((size_t)t * BB + r0) * G4 + ngl + (2 * g2) * HH;
        float2 xa0 = *reinterpret_cast<const float2*>(xwb);             // gate 2g2,   row 0
        float2 xb0 = *reinterpret_cast<const float2*>(xwb + HH);        // gate 2g2+1, row 0
        float2 xa1 = *reinterpret_cast<const float2*>(xwb + G4);        // gate 2g2,   row 1
        float2 xb1 = *reinterpret_cast<const float2*>(xwb + G4 + HH);   // gate 2g2+1, row 1
        __syncthreads();

        float2 acc[2][2];   // [gate-in-pair][row]
        acc[0][0] = xa0; acc[0][1] = xa1;
        acc[1][0] = xb0; acc[1][1] = xb1;

        const float* sr0 = sh[b_half * 2];
        const float* sr1 = sh[b_half * 2 + 1];
        const float4* Upair = reinterpret_cast<const float4*>(Us) + n_grp * 2 + g2;

#pragma unroll 4
        for (int k4 = 0; k4 < HH; k4 += 4) {
            float4 h0v = *reinterpret_cast<const float4*>(sr0 + k4);
            float4 h1v = *reinterpret_cast<const float4*>(sr1 + k4);
            const float h0a[4] = {h0v.x, h0v.y, h0v.z, h0v.w};
            const float h1a[4] = {h1v.x, h1v.y, h1v.z, h1v.w};
#pragma unroll
            for (int kk = 0; kk < 4; ++kk) {
                float4 u = Upair[(size_t)(k4 + kk) * 32];
                float2 uA = make_float2(u.x, u.y);
                float2 uB = make_float2(u.z, u.w);
                float2 hh0 = make_float2(h0a[kk], h0a[kk]);
                float2 hh1 = make_float2(h1a[kk], h1a[kk]);
                ffma2(acc[0][0], uA, hh0);
                ffma2(acc[0][1], uA, hh1);
                ffma2(acc[1][0], uB, hh0);
                ffma2(acc[1][1], uB, hh1);
            }
        }

        // gate exchange: g2==1 publishes z_g, z_o
        if (g2 == 1) {
            ex[0][inner] = acc[0][0];   // gate g, row 0
            ex[1][inner] = acc[1][0];   // gate o, row 0
            ex[2][inner] = acc[0][1];   // gate g, row 1
            ex[3][inner] = acc[1][1];   // gate o, row 1
        }
        __syncthreads();

        if (g2 == 0) {
#pragma unroll
            for (int bb = 0; bb < 2; ++bb) {
                float2 zi = acc[0][bb];
                float2 zf = acc[1][bb];
                float2 zg = ex[bb * 2][inner];
                float2 zo = ex[bb * 2 + 1][inner];
                float c0 = sigf(zf.x) * cst[bb].x + sigf(zi.x) * tanhfast(zg.x);
                float c1 = sigf(zf.y) * cst[bb].y + sigf(zi.y) * tanhfast(zg.y);
                cst[bb] = make_float2(c0, c1);
                float h0 = sigf(zo.x) * tanhfast(c0);
                float h1 = sigf(zo.y) * tanhfast(c1);
                int r = r0 + bb;
                __stcg(reinterpret_cast<float2*>(hWrite + (size_t)r * HH + ngl),
                       make_float2(h0, h1));
                if (write_seq)
                    *reinterpret_cast<float2*>(
                        g_seq + ((size_t)t * BB + r) * (2 * HH) + dir * HH + ngl) =
                        make_float2(h0, h1);
            }
        }

        grid_bar(grp, epoch);
    }
}

// ---------------- final dense + softmax ----------------
__global__ void final_k(const float* __restrict__ Wd, const float* __restrict__ bd,
                        float* __restrict__ out)
{
    int b = blockIdx.x, lane = threadIdx.x;
    const float* hf = g_state;                    // dir0 final h (parity buf0)
    const float* hb = g_state + 2 * BB * HH;      // dir1 final h (parity buf0)
    float acc[CC];
#pragma unroll
    for (int c = 0; c < CC; ++c) acc[c] = 0.f;
    for (int k = lane; k < 2 * HH; k += 32) {
        float hv = (k < HH) ? hf[(size_t)b * HH + k] : hb[(size_t)b * HH + k - HH];
        const float* w = Wd + (size_t)k * CC;
#pragma unroll
        for (int c = 0; c < CC; ++c) acc[c] = fmaf(hv, w[c], acc[c]);
    }
#pragma unroll
    for (int c = 0; c < CC; ++c)
#pragma unroll
        for (int o = 16; o; o >>= 1) acc[c] += __shfl_down_sync(0xffffffffu, acc[c], o);
    if (lane == 0) {
        float m = -1e30f;
#pragma unroll
        for (int c = 0; c < CC; ++c) { acc[c] += bd[c]; m = fmaxf(m, acc[c]); }
        float e[CC], s = 0.f;
#pragma unroll
        for (int c = 0; c < CC; ++c) { e[c] = expf(acc[c] - m); s += e[c]; }
        float inv = 1.f / s;
#pragma unroll
        for (int c = 0; c < CC; ++c) out[b * CC + c] = e[c] * inv;
    }
}

extern "C" void kernel_launch(void* const* d_in, const int* in_sizes, int n_in,
                              void* d_out, int out_size)
{
    const int*   x   = (const int*)  d_in[0];
    const float* emb = (const float*)d_in[1];
    const float* W1f = (const float*)d_in[2];
    const float* U1f = (const float*)d_in[3];
    const float* b1f = (const float*)d_in[4];
    const float* W1b = (const float*)d_in[5];
    const float* U1b = (const float*)d_in[6];
    const float* b1b = (const float*)d_in[7];
    const float* W2f = (const float*)d_in[8];
    const float* U2f = (const float*)d_in[9];
    const float* b2f = (const float*)d_in[10];
    const float* W2b = (const float*)d_in[11];
    const float* U2b = (const float*)d_in[12];
    const float* b2b = (const float*)d_in[13];
    const float* Wd  = (const float*)d_in[14];
    const float* bd  = (const float*)d_in[15];
    float* out = (float*)d_out;

    // Us 131072 + sh 16*260*4 = 16640 + ex 4*130*8 = 4160  -> 151872
    const int LSTM_SMEM = 131072 + 16 * 260 * 4 + 4 * 130 * 8;

    static int smem_set = 0;
    if (!smem_set) {
        cudaFuncSetAttribute(lstm_persist_k,
                             cudaFuncAttributeMaxDynamicSharedMemorySize, LSTM_SMEM);
        smem_set = 1;
    }

    embed_k<<<(MROWS * 32) / 256, 256>>>(x, emb);

    dim3 gg(MROWS / 128, G4 / 128);

    // layer 1
    gemm_k<<<gg, 256>>>(0, 0, W1f, b1f, DD);
    gemm_k<<<gg, 256>>>(0, 1, W1b, b1b, DD);
    lstm_persist_k<<<NCTA, 256, LSTM_SMEM>>>(U1f, U1b, 1);

    // layer 2
    gemm_k<<<gg, 256>>>(1, 0, W2f, b2f, 2 * HH);
    gemm_k<<<gg, 256>>>(1, 1, W2b, b2b, 2 * HH);
    lstm_persist_k<<<NCTA, 256, LSTM_SMEM>>>(U2f, U2b, 0);

    final_k<<<BB, 32>>>(Wd, bd, out);
}

// round 12
// speedup vs baseline: 1.0736x; 1.0736x over previous
#include <cuda_runtime.h>
#include <math.h>

#define TT 512
#define BB 128
#define DD 128
#define HH 256
#define CC 10
#define G4 1024
#define MROWS (TT*BB)
#define NCTA2 256         // recurrence grid: 2 dirs x 8 bt x 16 nt
#define NGRP 16           // CTAs per barrier group = one (dir, batch-tile)

// ---------------- static device scratch (no runtime allocation) ----------------
__device__ float g_e  [(size_t)MROWS * DD];
__device__ float g_XwF[(size_t)MROWS * G4];
__device__ float g_XwB[(size_t)MROWS * G4];
__device__ float g_seq[(size_t)MROWS * 2 * HH];
__device__ float g_state[4 * BB * HH];             // per dir: h parity buf0, buf1
__device__ unsigned g_bcount[16 * 32];
__device__ unsigned g_bepoch[16 * 32];

__device__ __forceinline__ void ffma2(float2 &d, float2 a, float2 b) {
    asm("fma.rn.f32x2 %0, %1, %2, %0;"
        : "+l"(*reinterpret_cast<unsigned long long*>(&d))
        : "l"(*reinterpret_cast<unsigned long long*>(&a)),
          "l"(*reinterpret_cast<unsigned long long*>(&b)));
}

__device__ __forceinline__ float sigf(float x) {
    return __fdividef(1.0f, 1.0f + __expf(-x));
}
__device__ __forceinline__ float tanhfast(float x) {
    return __fdividef(2.0f, 1.0f + __expf(-2.0f * x)) - 1.0f;
}

__device__ __forceinline__ void cpa16(unsigned dst, const void* src) {
    asm volatile("cp.async.cg.shared.global [%0], [%1], 16;" :: "r"(dst), "l"(src));
}
#define CPA_COMMIT() asm volatile("cp.async.commit_group;")
#define CPA_WAIT0()  asm volatile("cp.async.wait_group 0;")

__device__ __forceinline__ unsigned f2tf32(float x) {
    unsigned r; asm("cvt.rna.tf32.f32 %0, %1;" : "=r"(r) : "f"(x)); return r;
}
__device__ __forceinline__ void mma_tf32(float* c, const unsigned* a, const unsigned* b) {
    asm("mma.sync.aligned.m16n8k8.row.col.f32.tf32.tf32.f32 "
        "{%0,%1,%2,%3}, {%4,%5,%6,%7}, {%8,%9}, {%0,%1,%2,%3};"
        : "+f"(c[0]), "+f"(c[1]), "+f"(c[2]), "+f"(c[3])
        : "r"(a[0]), "r"(a[1]), "r"(a[2]), "r"(a[3]), "r"(b[0]), "r"(b[1]));
}

// per-group software barrier: 16 CTAs sharing one (dir, batch-tile)
__device__ __forceinline__ void grid_bar(int grp, unsigned &epoch) {
    __threadfence();
    __syncthreads();
    if (threadIdx.x == 0) {
        unsigned* cnt = &g_bcount[grp * 32];
        unsigned* ep  = &g_bepoch[grp * 32];
        if (atomicAdd(cnt, 1) == NGRP - 1) {
            atomicExch(cnt, 0);
            __threadfence();
            atomicAdd(ep, 1);
        } else {
            while (*(volatile unsigned*)ep == epoch) { }
        }
        epoch++;
    }
    __syncthreads();
}

// ---------------- embedding gather ----------------
__global__ void embed_k(const int* __restrict__ x, const float* __restrict__ emb) {
    int gid = blockIdx.x * blockDim.x + threadIdx.x;
    int r  = gid >> 5;
    int c4 = gid & 31;
    int t  = r >> 7;
    int b  = r & 127;
    int tok = x[b * TT + t];
    reinterpret_cast<float4*>(g_e)[(size_t)r * 32 + c4] =
        reinterpret_cast<const float4*>(emb)[(size_t)tok * 32 + c4];
}

// ---------------- 3xTF32 tensor-core GEMM + bias (unchanged from R7) ----------------
#define AS_LD 20
#define BS_LD 136
__global__ __launch_bounds__(256) void gemm_k(int a_sel, int c_sel,
        const float* __restrict__ W, const float* __restrict__ bias, int K)
{
    const float* A = a_sel ? g_seq : g_e;
    float*       C = c_sel ? g_XwB : g_XwF;

    __shared__ __align__(16) float As[2][128][AS_LD];
    __shared__ __align__(16) float Bs[2][16][BS_LD];

    const int m0   = blockIdx.x * 128;
    const int n0   = blockIdx.y * 128;
    const int tid  = threadIdx.x;
    const int lane = tid & 31;
    const int warp = tid >> 5;
    const int gid  = lane >> 2;
    const int tig  = lane & 3;
    const int wm   = warp & 3;
    const int wn   = warp >> 2;

    const unsigned sA = (unsigned)__cvta_generic_to_shared(&As[0][0][0]);
    const unsigned sB = (unsigned)__cvta_generic_to_shared(&Bs[0][0][0]);
    const unsigned bufA = 128 * AS_LD * 4;
    const unsigned bufB = 16 * BS_LD * 4;

    float acc[2][8][4];
#pragma unroll
    for (int mb = 0; mb < 2; ++mb)
#pragma unroll
        for (int nb = 0; nb < 8; ++nb)
#pragma unroll
            for (int r = 0; r < 4; ++r) acc[mb][nb][r] = 0.f;

    const int nk = K >> 4;

    auto load_tile = [&](int buf, int kt) {
#pragma unroll
        for (int i = 0; i < 2; ++i) {
            int id = tid + i * 256;
            int r = id >> 2, kq = id & 3;
            cpa16(sA + buf * bufA + (unsigned)((r * AS_LD + kq * 4) * 4),
                  A + (size_t)(m0 + r) * K + kt + kq * 4);
        }
#pragma unroll
        for (int i = 0; i < 2; ++i) {
            int id = tid + i * 256;
            int r = id >> 5, c4 = (id & 31) * 4;
            cpa16(sB + buf * bufB + (unsigned)((r * BS_LD + c4) * 4),
                  W + (size_t)(kt + r) * G4 + n0 + c4);
        }
        CPA_COMMIT();
    };

    load_tile(0, 0);
    CPA_WAIT0();
    __syncthreads();

    for (int kt = 0; kt < nk; ++kt) {
        const int cur = kt & 1;
        const bool more = (kt + 1) < nk;
        if (more) load_tile(cur ^ 1, (kt + 1) << 4);

#pragma unroll
        for (int kh = 0; kh < 2; ++kh) {
            const int k0 = kh * 8;
            unsigned ahi[2][4], alo[2][4];
#pragma unroll
            for (int mb = 0; mb < 2; ++mb) {
                const int rbase = wm * 32 + mb * 16 + gid;
#pragma unroll
                for (int r = 0; r < 4; ++r) {
                    float v = As[cur][rbase + (r & 1) * 8][k0 + tig + (r >> 1) * 4];
                    unsigned h = f2tf32(v);
                    ahi[mb][r] = h;
                    alo[mb][r] = f2tf32(v - __uint_as_float(h));
                }
            }
#pragma unroll
            for (int nb = 0; nb < 8; ++nb) {
                const int nc = wn * 64 + nb * 8 + gid;
                float b0 = Bs[cur][k0 + tig][nc];
                float b1 = Bs[cur][k0 + tig + 4][nc];
                unsigned bh[2], bl[2];
                bh[0] = f2tf32(b0); bl[0] = f2tf32(b0 - __uint_as_float(bh[0]));
                bh[1] = f2tf32(b1); bl[1] = f2tf32(b1 - __uint_as_float(bh[1]));
#pragma unroll
                for (int mb = 0; mb < 2; ++mb) mma_tf32(acc[mb][nb], ahi[mb], bh);
#pragma unroll
                for (int mb = 0; mb < 2; ++mb) mma_tf32(acc[mb][nb], ahi[mb], bl);
#pragma unroll
                for (int mb = 0; mb < 2; ++mb) mma_tf32(acc[mb][nb], alo[mb], bh);
            }
        }
        if (more) {
            CPA_WAIT0();
            __syncthreads();
        }
    }

#pragma unroll
    for (int mb = 0; mb < 2; ++mb) {
        const int row0 = m0 + wm * 32 + mb * 16 + gid;
#pragma unroll
        for (int nb = 0; nb < 8; ++nb) {
            const int col = n0 + wn * 64 + nb * 8 + tig * 2;
            float2 bv = *reinterpret_cast<const float2*>(bias + col);
            float2 v0 = make_float2(acc[mb][nb][0] + bv.x, acc[mb][nb][1] + bv.y);
            float2 v1 = make_float2(acc[mb][nb][2] + bv.x, acc[mb][nb][3] + bv.y);
            *reinterpret_cast<float2*>(C + (size_t)row0 * G4 + col)       = v0;
            *reinterpret_cast<float2*>(C + (size_t)(row0 + 8) * G4 + col) = v1;
        }
    }
}

// ---------------- persistent bidirectional LSTM: 16-col slices, 2 CTAs/SM ----------
// bid = dir*128 + bt*16 + nt (nt 0..15, 16 hidden cols per CTA). 256 CTAs -> 2 per
// SM (64KB U slice + 16.6KB h stage = 82KB smem) -> 2 warps/SMSP for latency hiding.
// Thread = 1 batch row x 2 cols x 4 gates; U smem as gate-pair float4 at
// [k][gp*8 + ng]: each LDS.128 is a contiguous 128B warp access (1 wavefront).
// acc is seeded with Xw. R7 exchange: global h double buffer + atomic group barrier.
__global__ __launch_bounds__(128, 2) void lstm_persist_k(
        const float* __restrict__ Uf, const float* __restrict__ Ub, int write_seq)
{
    extern __shared__ float smp[];
    float4* Upk = reinterpret_cast<float4*>(smp);              // [256][16] float4
    float (*sh)[260] = reinterpret_cast<float (*)[260]>(smp + 16384);  // h 16x260

    const int bid = blockIdx.x;
    const int dir = bid >> 7;
    const int bt  = (bid >> 4) & 7;
    const int nt  = bid & 15;
    const int grp = bid >> 4;                   // dir*8 + bt, 0..15
    const int tid = threadIdx.x;

    const float* U  = dir ? Ub : Uf;
    const float* Xw = dir ? g_XwB : g_XwF;
    float* hbuf = g_state + (size_t)dir * 2 * BB * HH;

    // U slice: Upk[k*16 + gp*8 + ng] =
    //   (U[k][2gp*HH+c], U[k][2gp*HH+c+1], U[k][(2gp+1)*HH+c], U[k][(2gp+1)*HH+c+1]),
    // c = nt*16 + ng*2.  gp blocks are contiguous (8 float4 = 128B) -> 1-wf loads.
    for (int i = tid; i < 4096; i += 128) {
        int k  = i >> 4;
        int f  = i & 15;
        int gp = f >> 3;
        int ng = f & 7;
        int col = nt * 16 + ng * 2;
        const float* src = U + (size_t)k * G4 + (2 * gp) * HH + col;
        float2 a = *reinterpret_cast<const float2*>(src);
        float2 b = *reinterpret_cast<const float2*>(src + HH);
        Upk[i] = make_float4(a.x, a.y, b.x, b.y);
    }

    // zero my (bt, nt) 16x16 patch of both h parity buffers
    for (int i = tid; i < 256; i += 128) {
        int r  = bt * 16 + (i >> 4);
        int cc = nt * 16 + (i & 15);
        __stcg(hbuf + (size_t)r * HH + cc, 0.f);
        __stcg(hbuf + (size_t)BB * HH + (size_t)r * HH + cc, 0.f);
    }

    unsigned epoch = 0;
    if (tid == 0) epoch = *(volatile unsigned*)&g_bepoch[grp * 32];
    grid_bar(grp, epoch);

    const int b16  = tid >> 3;         // row 0..15
    const int ng   = tid & 7;          // col pair 0..7
    const int nloc = ng * 2;
    const int ngl  = nt * 16 + nloc;
    const int r0   = bt * 16 + b16;

    float2 cst = make_float2(0.f, 0.f);

    for (int s = 0; s < TT; ++s) {
        const int t   = dir ? (TT - 1 - s) : s;
        const int par = s & 1;
        const float* hRead  = hbuf + (size_t)par * BB * HH;
        float*       hWrite = hbuf + (size_t)(par ^ 1) * BB * HH;

        // stage h tile (16 x 256): 1024 float4, 8 per thread
#pragma unroll
        for (int i = 0; i < 8; ++i) {
            int f = tid + i * 128;
            int r = f >> 6, cq = f & 63;
            *reinterpret_cast<float4*>(&sh[r][cq * 4]) =
                __ldcg(reinterpret_cast<const float4*>(
                    hRead + (size_t)(bt * 16 + r) * HH + cq * 4));
        }
        // Xw for my row, 4 gates x 2 cols -> seeds acc
        const float* xwb = Xw + ((size_t)t * BB + r0) * G4 + ngl;
        float2 acc[4];
#pragma unroll
        for (int g = 0; g < 4; ++g)
            acc[g] = *reinterpret_cast<const float2*>(xwb + g * HH);
        __syncthreads();

        const float* sr = sh[b16];
        const float4* up = Upk + ng;

#pragma unroll 8
        for (int k4 = 0; k4 < HH; k4 += 4) {
            float4 hv = *reinterpret_cast<const float4*>(sr + k4);
            const float ha[4] = {hv.x, hv.y, hv.z, hv.w};
#pragma unroll
            for (int kk = 0; kk < 4; ++kk) {
                const float4 u0 = up[(k4 + kk) * 16];       // gates i,f (cols n,n+1)
                const float4 u1 = up[(k4 + kk) * 16 + 8];   // gates g,o
                float2 hh = make_float2(ha[kk], ha[kk]);
                float2 a0 = make_float2(u0.x, u0.y);
                float2 a1 = make_float2(u0.z, u0.w);
                float2 a2 = make_float2(u1.x, u1.y);
                float2 a3 = make_float2(u1.z, u1.w);
                ffma2(acc[0], a0, hh);
                ffma2(acc[1], a1, hh);
                ffma2(acc[2], a2, hh);
                ffma2(acc[3], a3, hh);
            }
        }

        // gates + state update (1 row, 2 cols)
        float c0 = sigf(acc[1].x) * cst.x + sigf(acc[0].x) * tanhfast(acc[2].x);
        float c1 = sigf(acc[1].y) * cst.y + sigf(acc[0].y) * tanhfast(acc[2].y);
        cst = make_float2(c0, c1);
        float h0 = sigf(acc[3].x) * tanhfast(c0);
        float h1 = sigf(acc[3].y) * tanhfast(c1);
        __stcg(reinterpret_cast<float2*>(hWrite + (size_t)r0 * HH + ngl),
               make_float2(h0, h1));
        if (write_seq)
            *reinterpret_cast<float2*>(
                g_seq + ((size_t)t * BB + r0) * (2 * HH) + dir * HH + ngl) =
                make_float2(h0, h1);

        grid_bar(grp, epoch);
    }
}

// ---------------- final dense + softmax ----------------
__global__ void final_k(const float* __restrict__ Wd, const float* __restrict__ bd,
                        float* __restrict__ out)
{
    int b = blockIdx.x, lane = threadIdx.x;
    const float* hf = g_state;                    // dir0 final h (parity buf0)
    const float* hb = g_state + 2 * BB * HH;      // dir1 final h (parity buf0)
    float acc[CC];
#pragma unroll
    for (int c = 0; c < CC; ++c) acc[c] = 0.f;
    for (int k = lane; k < 2 * HH; k += 32) {
        float hv = (k < HH) ? hf[(size_t)b * HH + k] : hb[(size_t)b * HH + k - HH];
        const float* w = Wd + (size_t)k * CC;
#pragma unroll
        for (int c = 0; c < CC; ++c) acc[c] = fmaf(hv, w[c], acc[c]);
    }
#pragma unroll
    for (int c = 0; c < CC; ++c)
#pragma unroll
        for (int o = 16; o; o >>= 1) acc[c] += __shfl_down_sync(0xffffffffu, acc[c], o);
    if (lane == 0) {
        float m = -1e30f;
#pragma unroll
        for (int c = 0; c < CC; ++c) { acc[c] += bd[c]; m = fmaxf(m, acc[c]); }
        float e[CC], s = 0.f;
#pragma unroll
        for (int c = 0; c < CC; ++c) { e[c] = expf(acc[c] - m); s += e[c]; }
        float inv = 1.f / s;
#pragma unroll
        for (int c = 0; c < CC; ++c) out[b * CC + c] = e[c] * inv;
    }
}

extern "C" void kernel_launch(void* const* d_in, const int* in_sizes, int n_in,
                              void* d_out, int out_size)
{
    const int*   x   = (const int*)  d_in[0];
    const float* emb = (const float*)d_in[1];
    const float* W1f = (const float*)d_in[2];
    const float* U1f = (const float*)d_in[3];
    const float* b1f = (const float*)d_in[4];
    const float* W1b = (const float*)d_in[5];
    const float* U1b = (const float*)d_in[6];
    const float* b1b = (const float*)d_in[7];
    const float* W2f = (const float*)d_in[8];
    const float* U2f = (const float*)d_in[9];
    const float* b2f = (const float*)d_in[10];
    const float* W2b = (const float*)d_in[11];
    const float* U2b = (const float*)d_in[12];
    const float* b2b = (const float*)d_in[13];
    const float* Wd  = (const float*)d_in[14];
    const float* bd  = (const float*)d_in[15];
    float* out = (float*)d_out;

    // U slice 64KB + h stage 16*260*4 = 16640 -> 82176 bytes (2 CTAs/SM)
    const int LSTM_SMEM = 65536 + 16 * 260 * 4;

    static int smem_set = 0;
    if (!smem_set) {
        cudaFuncSetAttribute(lstm_persist_k,
                             cudaFuncAttributeMaxDynamicSharedMemorySize, LSTM_SMEM);
        smem_set = 1;
    }

    embed_k<<<(MROWS * 32) / 256, 256>>>(x, emb);

    dim3 gg(MROWS / 128, G4 / 128);

    // layer 1
    gemm_k<<<gg, 256>>>(0, 0, W1f, b1f, DD);
    gemm_k<<<gg, 256>>>(0, 1, W1b, b1b, DD);
    lstm_persist_k<<<NCTA2, 128, LSTM_SMEM>>>(U1f, U1b, 1);

    // layer 2
    gemm_k<<<gg, 256>>>(1, 0, W2f, b2f, 2 * HH);
    gemm_k<<<gg, 256>>>(1, 1, W2b, b2b, 2 * HH);
    lstm_persist_k<<<NCTA2, 128, LSTM_SMEM>>>(U2f, U2b, 0);

    final_k<<<BB, 32>>>(Wd, bd, out);
}